// round 2
// baseline (speedup 1.0000x reference)
#include <cuda_runtime.h>
#include <math.h>

#define NN      32768
#define KTOT    (3 * NN)
#define NPART   296
#define NTILES  (NN / 16)
#define EPSF    1e-5f

__device__ __constant__ float c_TPN = 0.022097086912079608f;  // 1/sqrt(16*128)
__device__ __constant__ float c_ISV = 0.08838834764831845f;   // 1/sqrt(128)

// ---------------- static device scratch ----------------
__device__ float g_part[NPART][128 * 128];
__device__ float g_G[128 * 128];
__device__ float g_Wc1[128 * 128];
__device__ float g_A[3][128 * 128];
__device__ float g_T[128 * 128];
__device__ float g_fn[3][128];
__device__ float g_c[128];

// ---------------------------------------------------------------------------
// Gram: G = Y^T Y with packed f32x2 FMAs (2 FMA per fma-pipe issue).
// ---------------------------------------------------------------------------
__global__ void __launch_bounds__(256, 2)
k_gram(const float* __restrict__ feat, const float* __restrict__ times) {
    __shared__ __align__(16) float B[48][132];
    unsigned long long acc[8][4];
#pragma unroll
    for (int i = 0; i < 8; i++)
#pragma unroll
        for (int j = 0; j < 4; j++) acc[i][j] = 0ull;

    const int tid = threadIdx.x;
    const int ty = tid >> 4;
    const int tx = tid & 15;

    for (int tile = blockIdx.x; tile < NTILES; tile += NPART) {
        __syncthreads();
        const int node0 = tile * 16;
#pragma unroll
        for (int i = 0; i < 6; i++) {
            const int f = tid + 256 * i;
            const int r = f / 96;
            const int q = f - r * 96;
            const int n = node0 + r;
            const float4 val =
                *(const float4*)(feat + (size_t)n * 512 + 128 + 4 * q);
            const float tm = __ldg(times + n);
            const int j = 4 * q;
            B[r * 3 + (j    ) % 3][(j    ) / 3] = tm * val.x;
            B[r * 3 + (j + 1) % 3][(j + 1) / 3] = tm * val.y;
            B[r * 3 + (j + 2) % 3][(j + 2) / 3] = tm * val.z;
            B[r * 3 + (j + 3) % 3][(j + 3) / 3] = tm * val.w;
        }
        __syncthreads();
#pragma unroll 2
        for (int k = 0; k < 48; k++) {
            const float4 a0 = *(const float4*)&B[k][ty * 8];
            const float4 a1 = *(const float4*)&B[k][ty * 8 + 4];
            const ulonglong2 q0 = *(const ulonglong2*)&B[k][tx * 8];
            const ulonglong2 q1 = *(const ulonglong2*)&B[k][tx * 8 + 4];
            const unsigned long long bp[4] = {q0.x, q0.y, q1.x, q1.y};
            const float a[8] = {a0.x, a0.y, a0.z, a0.w,
                                a1.x, a1.y, a1.z, a1.w};
#pragma unroll
            for (int i = 0; i < 8; i++) {
                unsigned long long ap;
                const unsigned int au = __float_as_uint(a[i]);
                asm("mov.b64 %0, {%1,%1};" : "=l"(ap) : "r"(au));
#pragma unroll
                for (int j = 0; j < 4; j++)
                    asm("fma.rn.f32x2 %0, %1, %2, %0;"
                        : "+l"(acc[i][j]) : "l"(ap), "l"(bp[j]));
            }
        }
    }

    float* outp = g_part[blockIdx.x];
#pragma unroll
    for (int i = 0; i < 8; i++)
#pragma unroll
        for (int j = 0; j < 4; j++) {
            unsigned int lo, hi;
            asm("mov.b64 {%0,%1}, %2;" : "=r"(lo), "=r"(hi) : "l"(acc[i][j]));
            outp[(ty * 8 + i) * 128 + tx * 8 + 2 * j]     = __uint_as_float(lo);
            outp[(ty * 8 + i) * 128 + tx * 8 + 2 * j + 1] = __uint_as_float(hi);
        }
}

__global__ void k_greduce() {
    const int i = blockIdx.x * blockDim.x + threadIdx.x;
    float s = 0.f;
#pragma unroll 8
    for (int p = 0; p < NPART; p++) s += g_part[p][i];
    g_G[i] = s;
}

__global__ void k_wc1(const float* __restrict__ W_time,
                      const float* __restrict__ W_tp1) {
    const int v = blockIdx.x, o = threadIdx.x;
    float acc = 0.f;
#pragma unroll
    for (int u = 0; u < 16; u++)
        acc = fmaf(W_time[u], W_tp1[u * 16384 + v * 128 + o], acc);
    g_Wc1[v * 128 + o] = acc * c_TPN;
}

// ---------------------------------------------------------------------------
// Generic 128x128 GEMM, weight tile in shared.
// mode 0: g_A[stage] = (Ain ⊙ d_{stage-1}) @ Wv[stage] * isv
//         (Ain = Wc1 for stage 0, else g_A[stage-1])
// mode 1: g_T = g_G @ g_A[stage]
// grid: 16 blocks = 8 rowblocks x 2 colhalves; 256 threads (16x16).
// ---------------------------------------------------------------------------
__global__ void __launch_bounds__(256)
k_mm(int mode, int stage, const float* __restrict__ Wv_all,
     const float* __restrict__ gamma_v) {
    __shared__ __align__(16) float Bs[128][68];
    __shared__ __align__(16) float As[16][132];

    const float* Ain = (mode == 0)
                           ? ((stage == 0) ? g_Wc1 : g_A[stage - 1])
                           : g_G;
    const float* Bg  = (mode == 0) ? (Wv_all + stage * 16384) : g_A[stage];
    float* C         = (mode == 0) ? g_A[stage] : g_T;
    const float scale = (mode == 0) ? c_ISV : 1.0f;
    const bool use_d = (mode == 0 && stage > 0);

    const int rb = blockIdx.x >> 1;
    const int cb = blockIdx.x & 1;

    // Load B tile: 128 x 64 (col half cb)
#pragma unroll
    for (int i = 0; i < 8; i++) {
        const int idx = threadIdx.x + 256 * i;  // 0..2047 float4 units
        const int w = idx >> 4;
        const int c4 = idx & 15;
        const float4 v = *(const float4*)(Bg + w * 128 + cb * 64 + c4 * 4);
        Bs[w][c4 * 4 + 0] = v.x;
        Bs[w][c4 * 4 + 1] = v.y;
        Bs[w][c4 * 4 + 2] = v.z;
        Bs[w][c4 * 4 + 3] = v.w;
    }
    // Load A tile: 16 rows x 128, applying d on contraction index
#pragma unroll
    for (int i = 0; i < 2; i++) {
        const int idx = threadIdx.x + 256 * i;  // 0..511
        const int r = idx >> 5;
        const int c4 = idx & 31;
        float4 v = *(const float4*)(Ain + (rb * 16 + r) * 128 + c4 * 4);
        if (use_d) {
            const int w0 = c4 * 4;
            const float* fn = g_fn[stage - 1];
            const float* g = gamma_v + (stage - 1) * 128;
            v.x *= g[w0 + 0] * rsqrtf(fn[w0 + 0] + EPSF);
            v.y *= g[w0 + 1] * rsqrtf(fn[w0 + 1] + EPSF);
            v.z *= g[w0 + 2] * rsqrtf(fn[w0 + 2] + EPSF);
            v.w *= g[w0 + 3] * rsqrtf(fn[w0 + 3] + EPSF);
        }
        As[r][c4 * 4 + 0] = v.x;
        As[r][c4 * 4 + 1] = v.y;
        As[r][c4 * 4 + 2] = v.z;
        As[r][c4 * 4 + 3] = v.w;
    }
    __syncthreads();

    const int r = threadIdx.x >> 4;
    const int c = threadIdx.x & 15;
    float a0 = 0.f, a1 = 0.f, a2 = 0.f, a3 = 0.f;
#pragma unroll 8
    for (int w = 0; w < 128; w++) {
        const float a = As[r][w];
        const float4 b = *(const float4*)&Bs[w][c * 4];
        a0 = fmaf(a, b.x, a0);
        a1 = fmaf(a, b.y, a1);
        a2 = fmaf(a, b.z, a2);
        a3 = fmaf(a, b.w, a3);
    }
    float* outp = C + (rb * 16 + r) * 128 + cb * 64 + c * 4;
    outp[0] = a0 * scale;
    outp[1] = a1 * scale;
    outp[2] = a2 * scale;
    outp[3] = a3 * scale;
}

// fn[stage][o] = sum_v A[v,o]*T[v,o] / 3N   (1 block, 512 threads)
__global__ void k_dot(int stage) {
    __shared__ float red[4][128];
    const int o = threadIdx.x & 127;
    const int g = threadIdx.x >> 7;
    const float* A = g_A[stage];
    float s = 0.f;
#pragma unroll 8
    for (int v = g * 32; v < g * 32 + 32; v++)
        s = fmaf(A[v * 128 + o], g_T[v * 128 + o], s);
    red[g][o] = s;
    __syncthreads();
    if (g == 0)
        g_fn[stage][o] =
            (red[0][o] + red[1][o] + red[2][o] + red[3][o]) * (1.0f / (float)KTOT);
}

// c[v] = isv * sum_o A2[v,o] * d2[o] * W_r[o]
__global__ void k_cvec(const float* __restrict__ gamma_v,
                       const float* __restrict__ W_r) {
    const int v = threadIdx.x;  // 128 threads, 1 block
    __shared__ float dw[128];
    dw[v] = gamma_v[2 * 128 + v] * rsqrtf(g_fn[2][v] + EPSF) * W_r[v] * c_ISV;
    __syncthreads();
    float acc = 0.f;
#pragma unroll 8
    for (int o = 0; o < 128; o++)
        acc = fmaf(g_A[2][v * 128 + o], dw[o], acc);
    g_c[v] = acc;
}

// out[n,m] = time_n * sum_v x_v[n,v,m] * c[v]   (one warp per node)
__global__ void k_out(const float* __restrict__ feat,
                      const float* __restrict__ times,
                      float* __restrict__ out) {
    const int gw = (blockIdx.x * blockDim.x + threadIdx.x) >> 5;
    const int lane = threadIdx.x & 31;
    if (gw >= NN) return;
    const float4* p = (const float4*)(feat + (size_t)gw * 512 + 128);
    float s0 = 0.f, s1 = 0.f, s2 = 0.f;
#pragma unroll
    for (int i = 0; i < 3; i++) {
        const int f4 = lane + 32 * i;
        const float4 x = p[f4];
        const int j = 4 * f4;
        const float comp[4] = {x.x, x.y, x.z, x.w};
#pragma unroll
        for (int e = 0; e < 4; e++) {
            const int jj = j + e;
            const float pr = comp[e] * g_c[jj / 3];
            const int m = jj % 3;
            s0 += (m == 0) ? pr : 0.f;
            s1 += (m == 1) ? pr : 0.f;
            s2 += (m == 2) ? pr : 0.f;
        }
    }
#pragma unroll
    for (int off = 16; off > 0; off >>= 1) {
        s0 += __shfl_xor_sync(0xffffffffu, s0, off);
        s1 += __shfl_xor_sync(0xffffffffu, s1, off);
        s2 += __shfl_xor_sync(0xffffffffu, s2, off);
    }
    if (lane == 0) {
        const float tm = times[gw];
        out[gw * 3 + 0] = tm * s0;
        out[gw * 3 + 1] = tm * s1;
        out[gw * 3 + 2] = tm * s2;
    }
}

// ---------------------------------------------------------------------------
extern "C" void kernel_launch(void* const* d_in, const int* in_sizes, int n_in,
                              void* d_out, int out_size) {
    const float* feat    = (const float*)d_in[0];
    const float* times   = (const float*)d_in[1];
    const float* W_time  = (const float*)d_in[2];
    const float* W_tp1   = (const float*)d_in[4];
    const float* Wv      = (const float*)d_in[6];
    const float* gamma_v = (const float*)d_in[9];
    const float* W_r     = (const float*)d_in[10];
    float* out = (float*)d_out;

    k_gram<<<NPART, 256>>>(feat, times);
    k_greduce<<<64, 256>>>();
    k_wc1<<<128, 128>>>(W_time, W_tp1);

    for (int s = 0; s < 3; s++) {
        k_mm<<<16, 256>>>(0, s, Wv, gamma_v);  // A_s
        k_mm<<<16, 256>>>(1, s, Wv, gamma_v);  // T = G @ A_s
        k_dot<<<1, 512>>>(s);                  // fn_s
    }
    k_cvec<<<1, 128>>>(gamma_v, W_r);

    k_out<<<(NN * 32) / 256, 256>>>(feat, times, out);
}